// round 12
// baseline (speedup 1.0000x reference)
#include <cuda_runtime.h>
#include <cuda_bf16.h>
#include <math.h>

#define D 256
#define K 5
#define THREADS 256
#define MIN_BLOCKS_PER_SM 5
#define BLOCKS 740                     // 148 SMs * 5 resident blocks = exactly one wave
#define WARPS_PER_BLOCK (THREADS / 32)
#define TOTAL_WARPS (BLOCKS * WARPS_PER_BLOCK)
#define RED_THREADS 512
#define NCAND (BLOCKS * K)             // 3700
#define PER_T ((NCAND + RED_THREADS - 1) / RED_THREADS)   // 8

// Scratch (static device globals -- no allocation allowed)
__device__ float g_cand_val[NCAND];
__device__ int   g_cand_idx[NCAND];

// tie-break matches jax top_k: higher value first; equal value -> lower index first
__device__ __forceinline__ bool better(float v, int i, float V, int I) {
    return (v > V) || (v == V && i < I);
}

__device__ __forceinline__ void insert_top5(float v, int i, float tv[K], int ti[K]) {
    if (!better(v, i, tv[K - 1], ti[K - 1])) return;
    tv[K - 1] = v; ti[K - 1] = i;
#pragma unroll
    for (int j = K - 1; j > 0; --j) {
        if (better(tv[j], ti[j], tv[j - 1], ti[j - 1])) {
            float fv = tv[j]; tv[j] = tv[j - 1]; tv[j - 1] = fv;
            int   fi = ti[j]; ti[j] = ti[j - 1]; ti[j - 1] = fi;
        }
    }
}

// -------- Kernel 1: scan (query norm fused, per-block top-5) --------
__global__ void __launch_bounds__(THREADS, MIN_BLOCKS_PER_SM)
knn_scan(const float* __restrict__ q, const float* __restrict__ emb, int n) {
    __shared__ float s_q[D];
    __shared__ float s_part[WARPS_PER_BLOCK];
    __shared__ float s_norm;
    __shared__ float mv[THREADS * K];
    __shared__ int   mi[THREADS * K];

    const int t    = threadIdx.x;
    const int lane = t & 31;

    // --- normalize query into smem (per block; L2-resident after first block) ---
    {
        float v = q[t];
        float sq = v * v;
#pragma unroll
        for (int off = 16; off > 0; off >>= 1)
            sq += __shfl_down_sync(0xffffffffu, sq, off);
        if (lane == 0) s_part[t >> 5] = sq;
        __syncthreads();
        if (t == 0) {
            float tot = 0.f;
#pragma unroll
            for (int i = 0; i < WARPS_PER_BLOCK; ++i) tot += s_part[i];
            s_norm = fmaxf(sqrtf(tot), 1e-12f);
        }
        __syncthreads();
        s_q[t] = v / s_norm;
        __syncthreads();
    }

    // allow the dependent reduce kernel to launch & park (hides its launch latency)
    cudaTriggerProgrammaticLaunchCompletion();

    const float4* sq4 = (const float4*)s_q;
    const float4 q0 = sq4[lane];
    const float4 q1 = sq4[lane + 32];

    float tv[K]; int ti[K];
#pragma unroll
    for (int j = 0; j < K; ++j) { tv[j] = -INFINITY; ti[j] = 0x7fffffff; }

    const int warp = (blockIdx.x * THREADS + t) >> 5;
    const int chunk = (n + TOTAL_WARPS - 1) / TOTAL_WARPS;
    int rbeg = warp * chunk;
    int rend = rbeg + chunk; if (rend > n) rend = n;
    if (rbeg > n) rbeg = n;

    const bool h16 = (lane & 16) != 0;
    const bool h8  = (lane & 8)  != 0;
    const int r_off = (h16 ? 1 : 0) + (h8 ? 2 : 0);
    const bool do_ins = (lane & 7) == 0;

    int row = rbeg;
    for (; row + 4 <= rend; row += 4) {
        float4 A[4], B[4];
#pragma unroll
        for (int r = 0; r < 4; ++r) {
            const float4* e = (const float4*)(emb + (size_t)(row + r) * D);
            A[r] = e[lane];
            B[r] = e[lane + 32];
        }
        float d[4];
#pragma unroll
        for (int r = 0; r < 4; ++r) {
            float s = fmaf(A[r].x, q0.x, fmaf(A[r].y, q0.y, fmaf(A[r].z, q0.z, A[r].w * q0.w)));
            d[r] = fmaf(B[r].x, q1.x, fmaf(B[r].y, q1.y, fmaf(B[r].z, q1.z, fmaf(B[r].w, q1.w, s))));
        }
        // 4-way warp reduce in 5 shuffles:
        float send01 = h16 ? d[0] : d[1];
        float s01 = (h16 ? d[1] : d[0]) + __shfl_xor_sync(0xffffffffu, send01, 16);
        float send23 = h16 ? d[2] : d[3];
        float s23 = (h16 ? d[3] : d[2]) + __shfl_xor_sync(0xffffffffu, send23, 16);
        float send = h8 ? s01 : s23;
        float s = (h8 ? s23 : s01) + __shfl_xor_sync(0xffffffffu, send, 8);
        s += __shfl_xor_sync(0xffffffffu, s, 4);
        s += __shfl_xor_sync(0xffffffffu, s, 2);
        s += __shfl_xor_sync(0xffffffffu, s, 1);
        // lanes 0,8,16,24 hold totals of rows row+0, row+2, row+1, row+3
        if (do_ins) insert_top5(s, row + r_off, tv, ti);
    }
    // remainder rows (<=3)
    for (; row < rend; ++row) {
        const float4* e = (const float4*)(emb + (size_t)row * D);
        float4 a = e[lane], b = e[lane + 32];
        float s = fmaf(a.x, q0.x, fmaf(a.y, q0.y, fmaf(a.z, q0.z, a.w * q0.w)));
        s = fmaf(b.x, q1.x, fmaf(b.y, q1.y, fmaf(b.z, q1.z, fmaf(b.w, q1.w, s))));
#pragma unroll
        for (int off = 16; off > 0; off >>= 1)
            s += __shfl_xor_sync(0xffffffffu, s, off);
        if (lane == 0) insert_top5(s, row, tv, ti);
    }

    // --- per-block merge of 256 per-thread lists -> block top-5 ---
#pragma unroll
    for (int j = 0; j < K; ++j) { mv[t * K + j] = tv[j]; mi[t * K + j] = ti[j]; }
    for (int sft = THREADS / 2; sft >= 1; sft >>= 1) {
        __syncthreads();
        if (t < sft) {
#pragma unroll
            for (int j = 0; j < K; ++j) { tv[j] = mv[t * K + j]; ti[j] = mi[t * K + j]; }
#pragma unroll
            for (int j = 0; j < K; ++j)
                insert_top5(mv[(t + sft) * K + j], mi[(t + sft) * K + j], tv, ti);
#pragma unroll
            for (int j = 0; j < K; ++j) { mv[t * K + j] = tv[j]; mi[t * K + j] = ti[j]; }
        }
    }
    __syncthreads();
    if (t == 0) {
#pragma unroll
        for (int j = 0; j < K; ++j) {
            g_cand_val[blockIdx.x * K + j] = mv[j];
            g_cand_idx[blockIdx.x * K + j] = mi[j];
        }
    }
}

// -------- Kernel 2: reduce (PDL: launches early, waits for scan grid) --------
__global__ void __launch_bounds__(RED_THREADS) knn_reduce(float* __restrict__ out) {
    __shared__ float sv[RED_THREADS * K];
    __shared__ int   si[RED_THREADS * K];
    const int t = threadIdx.x;

    // wait for the full scan grid to complete (all g_cand writes visible after this)
    cudaGridDependencySynchronize();

    // Phase 1: batched independent loads (full unroll -> max MLP, one latency wall)
    float cv[PER_T]; int ci[PER_T];
#pragma unroll
    for (int u = 0; u < PER_T; ++u) {
        int c = t + u * RED_THREADS;
        bool ok = c < NCAND;
        int cc = ok ? c : 0;
        cv[u] = __ldcg(&g_cand_val[cc]);
        ci[u] = __ldcg(&g_cand_idx[cc]);
        if (!ok) { cv[u] = -INFINITY; ci[u] = 0x7fffffff; }
    }

    // Phase 2: insert into local top-5 (8 dependent inserts)
    float tv[K]; int ti[K];
#pragma unroll
    for (int j = 0; j < K; ++j) { tv[j] = -INFINITY; ti[j] = 0x7fffffff; }
#pragma unroll
    for (int u = 0; u < PER_T; ++u)
        insert_top5(cv[u], ci[u], tv, ti);

    // Phase 3: smem tree merge
#pragma unroll
    for (int j = 0; j < K; ++j) { sv[t * K + j] = tv[j]; si[t * K + j] = ti[j]; }
    for (int s = RED_THREADS / 2; s >= 1; s >>= 1) {
        __syncthreads();
        if (t < s) {
#pragma unroll
            for (int j = 0; j < K; ++j) { tv[j] = sv[t * K + j]; ti[j] = si[t * K + j]; }
#pragma unroll
            for (int j = 0; j < K; ++j)
                insert_top5(sv[(t + s) * K + j], si[(t + s) * K + j], tv, ti);
#pragma unroll
            for (int j = 0; j < K; ++j) { sv[t * K + j] = tv[j]; si[t * K + j] = ti[j]; }
        }
    }
    __syncthreads();
    if (t == 0) {
#pragma unroll
        for (int j = 0; j < K; ++j) {
            out[j]     = (float)si[j];   // top_idx (reference tuple order: idx first)
            out[K + j] = sv[j];          // top_vals
        }
    }
}

extern "C" void kernel_launch(void* const* d_in, const int* in_sizes, int n_in,
                              void* d_out, int out_size) {
    const float* q   = (const float*)d_in[0];   // [1, 256]
    const float* emb = (const float*)d_in[1];   // [N, 256]
    const int n = in_sizes[1] / D;

    knn_scan<<<BLOCKS, THREADS>>>(q, emb, n);

    // PDL: reduce launches while scan runs; cudaGridDependencySynchronize()
    // inside the kernel enforces ordering + visibility.
    cudaLaunchConfig_t cfg = {};
    cfg.gridDim  = dim3(1, 1, 1);
    cfg.blockDim = dim3(RED_THREADS, 1, 1);
    cfg.dynamicSmemBytes = 0;
    cfg.stream = 0;                      // legacy default stream (same as <<<>>>)
    cudaLaunchAttribute attr[1];
    attr[0].id = cudaLaunchAttributeProgrammaticStreamSerialization;
    attr[0].val.programmaticStreamSerializationAllowed = 1;
    cfg.attrs = attr;
    cfg.numAttrs = 1;
    cudaLaunchKernelEx(&cfg, knn_reduce, (float*)d_out);
}

// round 14
// speedup vs baseline: 1.0061x; 1.0061x over previous
#include <cuda_runtime.h>
#include <cuda_bf16.h>
#include <math.h>

#define D 256
#define K 5
#define THREADS 256
#define MIN_BLOCKS_PER_SM 5
#define BLOCKS 735                     // 147 SMs * 5 blocks; leaves 1 SM for the parked PDL reduce
#define WARPS_PER_BLOCK (THREADS / 32)
#define TOTAL_WARPS (BLOCKS * WARPS_PER_BLOCK)
#define RED_THREADS 512
#define NCAND (BLOCKS * K)             // 3675
#define PER_T ((NCAND + RED_THREADS - 1) / RED_THREADS)   // 8

// Scratch (static device globals -- no allocation allowed)
__device__ float g_cand_val[NCAND];
__device__ int   g_cand_idx[NCAND];

// tie-break matches jax top_k: higher value first; equal value -> lower index first
__device__ __forceinline__ bool better(float v, int i, float V, int I) {
    return (v > V) || (v == V && i < I);
}

__device__ __forceinline__ void insert_top5(float v, int i, float tv[K], int ti[K]) {
    if (!better(v, i, tv[K - 1], ti[K - 1])) return;
    tv[K - 1] = v; ti[K - 1] = i;
#pragma unroll
    for (int j = K - 1; j > 0; --j) {
        if (better(tv[j], ti[j], tv[j - 1], ti[j - 1])) {
            float fv = tv[j]; tv[j] = tv[j - 1]; tv[j - 1] = fv;
            int   fi = ti[j]; ti[j] = ti[j - 1]; ti[j - 1] = fi;
        }
    }
}

// -------- Kernel 1: scan (query norm fused, per-block top-5) --------
__global__ void __launch_bounds__(THREADS, MIN_BLOCKS_PER_SM)
knn_scan(const float* __restrict__ q, const float* __restrict__ emb, int n) {
    __shared__ float s_q[D];
    __shared__ float s_part[WARPS_PER_BLOCK];
    __shared__ float s_norm;
    __shared__ float mv[THREADS * K];
    __shared__ int   mi[THREADS * K];

    // fire ASAP: lets the dependent reduce kernel launch & park on the free SM
    cudaTriggerProgrammaticLaunchCompletion();

    const int t    = threadIdx.x;
    const int lane = t & 31;

    // --- normalize query into smem (per block; L2-resident after first block) ---
    {
        float v = q[t];
        float sq = v * v;
#pragma unroll
        for (int off = 16; off > 0; off >>= 1)
            sq += __shfl_down_sync(0xffffffffu, sq, off);
        if (lane == 0) s_part[t >> 5] = sq;
        __syncthreads();
        if (t == 0) {
            float tot = 0.f;
#pragma unroll
            for (int i = 0; i < WARPS_PER_BLOCK; ++i) tot += s_part[i];
            s_norm = fmaxf(sqrtf(tot), 1e-12f);
        }
        __syncthreads();
        s_q[t] = v / s_norm;
        __syncthreads();
    }

    const float4* sq4 = (const float4*)s_q;
    const float4 q0 = sq4[lane];
    const float4 q1 = sq4[lane + 32];

    float tv[K]; int ti[K];
#pragma unroll
    for (int j = 0; j < K; ++j) { tv[j] = -INFINITY; ti[j] = 0x7fffffff; }

    const int warp = (blockIdx.x * THREADS + t) >> 5;
    const int chunk = (n + TOTAL_WARPS - 1) / TOTAL_WARPS;
    int rbeg = warp * chunk;
    int rend = rbeg + chunk; if (rend > n) rend = n;
    if (rbeg > n) rbeg = n;

    const bool h16 = (lane & 16) != 0;
    const bool h8  = (lane & 8)  != 0;
    const int r_off = (h16 ? 1 : 0) + (h8 ? 2 : 0);
    const bool do_ins = (lane & 7) == 0;

    int row = rbeg;
    for (; row + 4 <= rend; row += 4) {
        float4 A[4], B[4];
#pragma unroll
        for (int r = 0; r < 4; ++r) {
            const float4* e = (const float4*)(emb + (size_t)(row + r) * D);
            A[r] = e[lane];
            B[r] = e[lane + 32];
        }
        float d[4];
#pragma unroll
        for (int r = 0; r < 4; ++r) {
            float s = fmaf(A[r].x, q0.x, fmaf(A[r].y, q0.y, fmaf(A[r].z, q0.z, A[r].w * q0.w)));
            d[r] = fmaf(B[r].x, q1.x, fmaf(B[r].y, q1.y, fmaf(B[r].z, q1.z, fmaf(B[r].w, q1.w, s))));
        }
        // 4-way warp reduce in 5 shuffles:
        float send01 = h16 ? d[0] : d[1];
        float s01 = (h16 ? d[1] : d[0]) + __shfl_xor_sync(0xffffffffu, send01, 16);
        float send23 = h16 ? d[2] : d[3];
        float s23 = (h16 ? d[3] : d[2]) + __shfl_xor_sync(0xffffffffu, send23, 16);
        float send = h8 ? s01 : s23;
        float s = (h8 ? s23 : s01) + __shfl_xor_sync(0xffffffffu, send, 8);
        s += __shfl_xor_sync(0xffffffffu, s, 4);
        s += __shfl_xor_sync(0xffffffffu, s, 2);
        s += __shfl_xor_sync(0xffffffffu, s, 1);
        // lanes 0,8,16,24 hold totals of rows row+0, row+2, row+1, row+3
        if (do_ins) insert_top5(s, row + r_off, tv, ti);
    }
    // remainder rows (<=3)
    for (; row < rend; ++row) {
        const float4* e = (const float4*)(emb + (size_t)row * D);
        float4 a = e[lane], b = e[lane + 32];
        float s = fmaf(a.x, q0.x, fmaf(a.y, q0.y, fmaf(a.z, q0.z, a.w * q0.w)));
        s = fmaf(b.x, q1.x, fmaf(b.y, q1.y, fmaf(b.z, q1.z, fmaf(b.w, q1.w, s))));
#pragma unroll
        for (int off = 16; off > 0; off >>= 1)
            s += __shfl_xor_sync(0xffffffffu, s, off);
        if (lane == 0) insert_top5(s, row, tv, ti);
    }

    // --- per-block merge of 256 per-thread lists -> block top-5 ---
#pragma unroll
    for (int j = 0; j < K; ++j) { mv[t * K + j] = tv[j]; mi[t * K + j] = ti[j]; }
    for (int sft = THREADS / 2; sft >= 1; sft >>= 1) {
        __syncthreads();
        if (t < sft) {
#pragma unroll
            for (int j = 0; j < K; ++j) { tv[j] = mv[t * K + j]; ti[j] = mi[t * K + j]; }
#pragma unroll
            for (int j = 0; j < K; ++j)
                insert_top5(mv[(t + sft) * K + j], mi[(t + sft) * K + j], tv, ti);
#pragma unroll
            for (int j = 0; j < K; ++j) { mv[t * K + j] = tv[j]; mi[t * K + j] = ti[j]; }
        }
    }
    __syncthreads();
    if (t == 0) {
#pragma unroll
        for (int j = 0; j < K; ++j) {
            g_cand_val[blockIdx.x * K + j] = mv[j];
            g_cand_idx[blockIdx.x * K + j] = mi[j];
        }
    }
}

// -------- Kernel 2: reduce (PDL: launches early, waits for scan grid) --------
__global__ void __launch_bounds__(RED_THREADS) knn_reduce(float* __restrict__ out) {
    __shared__ float sv[RED_THREADS * K];
    __shared__ int   si[RED_THREADS * K];
    const int t = threadIdx.x;

    // wait for the full scan grid to complete (all g_cand writes visible after this)
    cudaGridDependencySynchronize();

    // Phase 1: batched independent loads (full unroll -> max MLP, one latency wall)
    float cv[PER_T]; int ci[PER_T];
#pragma unroll
    for (int u = 0; u < PER_T; ++u) {
        int c = t + u * RED_THREADS;
        bool ok = c < NCAND;
        int cc = ok ? c : 0;
        cv[u] = __ldcg(&g_cand_val[cc]);
        ci[u] = __ldcg(&g_cand_idx[cc]);
        if (!ok) { cv[u] = -INFINITY; ci[u] = 0x7fffffff; }
    }

    // Phase 2: insert into local top-5 (8 dependent inserts)
    float tv[K]; int ti[K];
#pragma unroll
    for (int j = 0; j < K; ++j) { tv[j] = -INFINITY; ti[j] = 0x7fffffff; }
#pragma unroll
    for (int u = 0; u < PER_T; ++u)
        insert_top5(cv[u], ci[u], tv, ti);

    // Phase 3: smem tree merge
#pragma unroll
    for (int j = 0; j < K; ++j) { sv[t * K + j] = tv[j]; si[t * K + j] = ti[j]; }
    for (int s = RED_THREADS / 2; s >= 1; s >>= 1) {
        __syncthreads();
        if (t < s) {
#pragma unroll
            for (int j = 0; j < K; ++j) { tv[j] = sv[t * K + j]; ti[j] = si[t * K + j]; }
#pragma unroll
            for (int j = 0; j < K; ++j)
                insert_top5(sv[(t + s) * K + j], si[(t + s) * K + j], tv, ti);
#pragma unroll
            for (int j = 0; j < K; ++j) { sv[t * K + j] = tv[j]; si[t * K + j] = ti[j]; }
        }
    }
    __syncthreads();
    if (t == 0) {
#pragma unroll
        for (int j = 0; j < K; ++j) {
            out[j]     = (float)si[j];   // top_idx (reference tuple order: idx first)
            out[K + j] = sv[j];          // top_vals
        }
    }
}

extern "C" void kernel_launch(void* const* d_in, const int* in_sizes, int n_in,
                              void* d_out, int out_size) {
    const float* q   = (const float*)d_in[0];   // [1, 256]
    const float* emb = (const float*)d_in[1];   // [N, 256]
    const int n = in_sizes[1] / D;

    knn_scan<<<BLOCKS, THREADS>>>(q, emb, n);

    // PDL: reduce launches while scan runs; cudaGridDependencySynchronize()
    // inside the kernel enforces ordering + visibility.
    cudaLaunchConfig_t cfg = {};
    cfg.gridDim  = dim3(1, 1, 1);
    cfg.blockDim = dim3(RED_THREADS, 1, 1);
    cfg.dynamicSmemBytes = 0;
    cfg.stream = 0;                      // legacy default stream (same as <<<>>>)
    cudaLaunchAttribute attr[1];
    attr[0].id = cudaLaunchAttributeProgrammaticStreamSerialization;
    attr[0].val.programmaticStreamSerializationAllowed = 1;
    cfg.attrs = attr;
    cfg.numAttrs = 1;
    cudaLaunchKernelEx(&cfg, knn_reduce, (float*)d_out);
}

// round 15
// speedup vs baseline: 1.0603x; 1.0539x over previous
#include <cuda_runtime.h>
#include <cuda_bf16.h>
#include <math.h>

#define D 256
#define K 5
#define THREADS 256
#define MIN_BLOCKS_PER_SM 5
#define BLOCKS 740                     // 148 SMs * 5 resident blocks = exactly one wave
#define WARPS_PER_BLOCK (THREADS / 32)
#define TOTAL_WARPS (BLOCKS * WARPS_PER_BLOCK)

// Lock-free global top-5 (static device global -- zero-initialized, no allocation)
__device__ unsigned long long g_top5[K];

// tie-break matches jax top_k: higher value first; equal value -> lower index first
__device__ __forceinline__ bool better(float v, int i, float V, int I) {
    return (v > V) || (v == V && i < I);
}

__device__ __forceinline__ void insert_top5(float v, int i, float tv[K], int ti[K]) {
    if (!better(v, i, tv[K - 1], ti[K - 1])) return;
    tv[K - 1] = v; ti[K - 1] = i;
#pragma unroll
    for (int j = K - 1; j > 0; --j) {
        if (better(tv[j], ti[j], tv[j - 1], ti[j - 1])) {
            float fv = tv[j]; tv[j] = tv[j - 1]; tv[j - 1] = fv;
            int   fi = ti[j]; ti[j] = ti[j - 1]; ti[j - 1] = fi;
        }
    }
}

// pack (value, idx) into one sortable u64: bigger key = better candidate.
// high 32: monotonic float transform; low 32: ~idx (smaller idx -> larger key).
__device__ __forceinline__ unsigned long long pack_key(float v, int idx) {
    unsigned int b = __float_as_uint(v);
    b = (b & 0x80000000u) ? ~b : (b | 0x80000000u);
    return ((unsigned long long)b << 32) | (unsigned long long)(~(unsigned int)idx);
}

// -------- Kernel 1: scan (query norm fused, per-block top-5, atomic global merge) ----
__global__ void __launch_bounds__(THREADS, MIN_BLOCKS_PER_SM)
knn_scan(const float* __restrict__ q, const float* __restrict__ emb, int n) {
    __shared__ float s_q[D];
    __shared__ float s_part[WARPS_PER_BLOCK];
    __shared__ float s_norm;
    __shared__ float mv[THREADS * K];
    __shared__ int   mi[THREADS * K];

    const int t    = threadIdx.x;
    const int lane = t & 31;

    // --- normalize query into smem (per block; L2-resident after first block) ---
    {
        float v = q[t];
        float sq = v * v;
#pragma unroll
        for (int off = 16; off > 0; off >>= 1)
            sq += __shfl_down_sync(0xffffffffu, sq, off);
        if (lane == 0) s_part[t >> 5] = sq;
        __syncthreads();
        if (t == 0) {
            float tot = 0.f;
#pragma unroll
            for (int i = 0; i < WARPS_PER_BLOCK; ++i) tot += s_part[i];
            s_norm = fmaxf(sqrtf(tot), 1e-12f);
        }
        __syncthreads();
        s_q[t] = v / s_norm;
        __syncthreads();
    }

    const float4* sq4 = (const float4*)s_q;
    const float4 q0 = sq4[lane];
    const float4 q1 = sq4[lane + 32];

    float tv[K]; int ti[K];
#pragma unroll
    for (int j = 0; j < K; ++j) { tv[j] = -INFINITY; ti[j] = 0x7fffffff; }

    const int warp = (blockIdx.x * THREADS + t) >> 5;
    const int chunk = (n + TOTAL_WARPS - 1) / TOTAL_WARPS;
    int rbeg = warp * chunk;
    int rend = rbeg + chunk; if (rend > n) rend = n;
    if (rbeg > n) rbeg = n;

    const bool h16 = (lane & 16) != 0;
    const bool h8  = (lane & 8)  != 0;
    const int r_off = (h16 ? 1 : 0) + (h8 ? 2 : 0);
    const bool do_ins = (lane & 7) == 0;

    int row = rbeg;
    for (; row + 4 <= rend; row += 4) {
        float4 A[4], B[4];
#pragma unroll
        for (int r = 0; r < 4; ++r) {
            const float4* e = (const float4*)(emb + (size_t)(row + r) * D);
            A[r] = e[lane];
            B[r] = e[lane + 32];
        }
        float d[4];
#pragma unroll
        for (int r = 0; r < 4; ++r) {
            float s = fmaf(A[r].x, q0.x, fmaf(A[r].y, q0.y, fmaf(A[r].z, q0.z, A[r].w * q0.w)));
            d[r] = fmaf(B[r].x, q1.x, fmaf(B[r].y, q1.y, fmaf(B[r].z, q1.z, fmaf(B[r].w, q1.w, s))));
        }
        // 4-way warp reduce in 5 shuffles:
        float send01 = h16 ? d[0] : d[1];
        float s01 = (h16 ? d[1] : d[0]) + __shfl_xor_sync(0xffffffffu, send01, 16);
        float send23 = h16 ? d[2] : d[3];
        float s23 = (h16 ? d[3] : d[2]) + __shfl_xor_sync(0xffffffffu, send23, 16);
        float send = h8 ? s01 : s23;
        float s = (h8 ? s23 : s01) + __shfl_xor_sync(0xffffffffu, send, 8);
        s += __shfl_xor_sync(0xffffffffu, s, 4);
        s += __shfl_xor_sync(0xffffffffu, s, 2);
        s += __shfl_xor_sync(0xffffffffu, s, 1);
        // lanes 0,8,16,24 hold totals of rows row+0, row+2, row+1, row+3
        if (do_ins) insert_top5(s, row + r_off, tv, ti);
    }
    // remainder rows (<=3)
    for (; row < rend; ++row) {
        const float4* e = (const float4*)(emb + (size_t)row * D);
        float4 a = e[lane], b = e[lane + 32];
        float s = fmaf(a.x, q0.x, fmaf(a.y, q0.y, fmaf(a.z, q0.z, a.w * q0.w)));
        s = fmaf(b.x, q1.x, fmaf(b.y, q1.y, fmaf(b.z, q1.z, fmaf(b.w, q1.w, s))));
#pragma unroll
        for (int off = 16; off > 0; off >>= 1)
            s += __shfl_xor_sync(0xffffffffu, s, off);
        if (lane == 0) insert_top5(s, row, tv, ti);
    }

    // --- per-block merge of 256 per-thread lists -> block top-5 ---
#pragma unroll
    for (int j = 0; j < K; ++j) { mv[t * K + j] = tv[j]; mi[t * K + j] = ti[j]; }
    for (int sft = THREADS / 2; sft >= 1; sft >>= 1) {
        __syncthreads();
        if (t < sft) {
#pragma unroll
            for (int j = 0; j < K; ++j) { tv[j] = mv[t * K + j]; ti[j] = mi[t * K + j]; }
#pragma unroll
            for (int j = 0; j < K; ++j)
                insert_top5(mv[(t + sft) * K + j], mi[(t + sft) * K + j], tv, ti);
#pragma unroll
            for (int j = 0; j < K; ++j) { mv[t * K + j] = tv[j]; mi[t * K + j] = ti[j]; }
        }
    }
    __syncthreads();

    // --- lock-free global merge: threads 0..4 insert block candidates via
    //     atomicMax cascade. Final slots = exact global top-5 (order-independent:
    //     every displaced value is re-inserted downstream, so slot j ends as the
    //     (j+1)-th max). Early-skip is safe: slots grow monotonically. ---
    if (t < K) {
        unsigned long long key = pack_key(mv[t], mi[t]);
        volatile unsigned long long* vt = (volatile unsigned long long*)g_top5;
        if (key > vt[K - 1]) {
#pragma unroll
            for (int j = 0; j < K; ++j) {
                unsigned long long old = atomicMax(&g_top5[j], key);
                if (old < key) key = old;       // carry displaced value down
                if (key == 0ull) break;         // nothing left to place
            }
        }
    }
}

// -------- Kernel 2: trivial finalize (decode 5 slots, write output, reset) --------
__global__ void knn_finalize(float* __restrict__ out) {
    if (threadIdx.x == 0) {
#pragma unroll
        for (int j = 0; j < K; ++j) {
            unsigned long long k = g_top5[j];
            unsigned int hb = (unsigned int)(k >> 32);
            unsigned int lb = (unsigned int)k;
            int idx = (int)(~lb);
            unsigned int vb = (hb & 0x80000000u) ? (hb & 0x7FFFFFFFu) : ~hb;
            out[j]     = (float)idx;            // top_idx (reference tuple order: idx first)
            out[K + j] = __uint_as_float(vb);   // top_vals
            g_top5[j] = 0ull;                   // reset for next graph replay
        }
    }
}

extern "C" void kernel_launch(void* const* d_in, const int* in_sizes, int n_in,
                              void* d_out, int out_size) {
    const float* q   = (const float*)d_in[0];   // [1, 256]
    const float* emb = (const float*)d_in[1];   // [N, 256]
    const int n = in_sizes[1] / D;

    knn_scan<<<BLOCKS, THREADS>>>(q, emb, n);
    knn_finalize<<<1, 32>>>((float*)d_out);
}